// round 6
// baseline (speedup 1.0000x reference)
#include <cuda_runtime.h>

#define N_NODES 50000
#define IN_F    256
#define OUT_F   64
#define ROWS_PER_BLK 32
#define MAX_E   800000
#define SCAN_T  1024

// ---- __device__ scratch (alloc-guard-safe) ----
__device__ __align__(16) float g_miu[N_NODES * OUT_F];   // miu*att
__device__ __align__(16) float g_sig[N_NODES * OUT_F];   // sigma*att^2
__device__ int  g_cnt[N_NODES];        // per-dst degree
__device__ int  g_off[N_NODES + 1];    // CSR row offsets
__device__ int  g_cur[N_NODES];        // fill cursors
__device__ __align__(16) int4 g_edges[MAX_E];  // {src, a1_bits, a2_bits, pad}
__device__ int  g_is64;

// ---------------------------------------------------------------------------
// Dtype probe: reference declares int64 indices but default-JAX downgrades to
// int32. 32 consecutive int64 reads all landing in [0,N) only if truly int64.
// ---------------------------------------------------------------------------
__global__ void probe_kernel(const void* __restrict__ esrc)
{
    const long long* p = (const long long*)esrc;
    int ok64 = 1;
    for (int i = 0; i < 32; i++) {
        long long v = p[i];
        if (v < 0 || v >= N_NODES) { ok64 = 0; break; }
    }
    g_is64 = ok64;
}

__device__ __forceinline__ int load_idx(const void* p, int i, int is64)
{
    return is64 ? (int)((const long long*)p)[i] : ((const int*)p)[i];
}

// ---- CSR build ----
__global__ __launch_bounds__(256) void zero_kernel()
{
    const int i = blockIdx.x * 256 + threadIdx.x;
    if (i < N_NODES) g_cnt[i] = 0;
}

__global__ __launch_bounds__(256) void hist_kernel(const void* __restrict__ edst, int E)
{
    const int i = blockIdx.x * 256 + threadIdx.x;
    if (i >= E) return;
    const int d = load_idx(edst, i, g_is64);
    if ((unsigned)d < N_NODES) atomicAdd(&g_cnt[d], 1);
}

// Single-block exclusive scan of g_cnt[0..N) -> g_off, g_cur; g_off[N] = total.
__global__ __launch_bounds__(SCAN_T) void scan_kernel()
{
    __shared__ int sp[SCAN_T];
    const int t = threadIdx.x;
    const int CHUNK = (N_NODES + SCAN_T - 1) / SCAN_T;   // 49
    const int beg = t * CHUNK;
    const int end = min(beg + CHUNK, N_NODES);

    int sum = 0;
    for (int i = beg; i < end; i++) sum += g_cnt[i];
    sp[t] = sum;
    __syncthreads();

    // Hillis–Steele inclusive scan over 1024 partials
    for (int off = 1; off < SCAN_T; off <<= 1) {
        int v = (t >= off) ? sp[t - off] : 0;
        __syncthreads();
        sp[t] += v;
        __syncthreads();
    }

    int run = sp[t] - sum;   // exclusive prefix for this chunk
    for (int i = beg; i < end; i++) {
        const int c = g_cnt[i];
        g_off[i] = run;
        g_cur[i] = run;
        run += c;
    }
    if (t == SCAN_T - 1) g_off[N_NODES] = sp[SCAN_T - 1];
}

__global__ __launch_bounds__(256) void fill_kernel(
    const void* __restrict__ esrc, const void* __restrict__ edst,
    const float* __restrict__ a1, const float* __restrict__ a2, int E)
{
    const int i = blockIdx.x * 256 + threadIdx.x;
    if (i >= E) return;
    const int is64 = g_is64;
    const int s = load_idx(esrc, i, is64);
    const int d = load_idx(edst, i, is64);
    if ((unsigned)s >= N_NODES || (unsigned)d >= N_NODES) return;
    const int pos = atomicAdd(&g_cur[d], 1);
    g_edges[pos] = make_int4(s, __float_as_int(__ldg(a1 + i)),
                                __float_as_int(__ldg(a2 + i)), 0);
}

// ---------------------------------------------------------------------------
// Kernel A: fused dual-GEMM + activations (unchanged; at FFMA roofline).
// ---------------------------------------------------------------------------
__global__ __launch_bounds__(256) void gemm_act_kernel(
    const float* __restrict__ feat,
    const float* __restrict__ wm,
    const float* __restrict__ ws)
{
    __shared__ float fs[ROWS_PER_BLK * IN_F];
    const int row0 = blockIdx.x * ROWS_PER_BLK;
    const int tid  = threadIdx.x;
    const int nrows = min(ROWS_PER_BLK, N_NODES - row0);

    {
        const float4* gf  = (const float4*)(feat + (size_t)row0 * IN_F);
        float4*       fs4 = (float4*)fs;
        const int total4  = nrows * (IN_F / 4);
        for (int i = tid; i < total4; i += 256) fs4[i] = gf[i];
    }
    __syncthreads();

    const int f  = tid & 63;
    const int rg = tid >> 6;

    float accm[8], accs[8];
#pragma unroll
    for (int r = 0; r < 8; r++) { accm[r] = 0.f; accs[r] = 0.f; }

    const float4* fs4 = (const float4*)fs;

    for (int k = 0; k < IN_F; k += 4) {
        const float wm0 = __ldg(&wm[(k + 0) * OUT_F + f]);
        const float wm1 = __ldg(&wm[(k + 1) * OUT_F + f]);
        const float wm2 = __ldg(&wm[(k + 2) * OUT_F + f]);
        const float wm3 = __ldg(&wm[(k + 3) * OUT_F + f]);
        const float ws0 = __ldg(&ws[(k + 0) * OUT_F + f]);
        const float ws1 = __ldg(&ws[(k + 1) * OUT_F + f]);
        const float ws2 = __ldg(&ws[(k + 2) * OUT_F + f]);
        const float ws3 = __ldg(&ws[(k + 3) * OUT_F + f]);
#pragma unroll
        for (int r = 0; r < 8; r++) {
            const float4 fv = fs4[(rg * 8 + r) * (IN_F / 4) + (k >> 2)];
            accm[r] = fmaf(fv.x, wm0, fmaf(fv.y, wm1, fmaf(fv.z, wm2, fmaf(fv.w, wm3, accm[r]))));
            accs[r] = fmaf(fv.x, ws0, fmaf(fv.y, ws1, fmaf(fv.z, ws2, fmaf(fv.w, ws3, accs[r]))));
        }
    }

#pragma unroll
    for (int r = 0; r < 8; r++) {
        const int row = row0 + rg * 8 + r;
        if (row < N_NODES) {
            const float m   = accm[r];
            const float mi  = (m > 0.f) ? m : (expf(m) - 1.f);   // ELU
            const float s   = (accs[r] > 0.f) ? accs[r] : 0.f;   // ReLU
            const float att = expf(-s);                          // GAMMA=1
            g_miu[row * OUT_F + f] = mi * att;
            g_sig[row * OUT_F + f] = s * att * att;
        }
    }
}

// ---------------------------------------------------------------------------
// Kernel B: CSR gather — one warp per dst node, ZERO atomics.
//   lanes 0..15  accumulate the 16 float4 chunks of miu_out[d]
//   lanes 16..31 accumulate the 16 float4 chunks of sigma_out[d]
// Edge records are 16B broadcast loads; message rows are L2-resident (25.6MB).
// Writes every output element -> no output memset needed.
// ---------------------------------------------------------------------------
__global__ __launch_bounds__(256) void gather_kernel(float* __restrict__ out)
{
    const int w = (blockIdx.x * 256 + threadIdx.x) >> 5;   // dst node
    if (w >= N_NODES) return;
    const int lane  = threadIdx.x & 31;
    const int c     = lane & 15;
    const bool isMiu = lane < 16;

    const int beg = g_off[w];
    const int end = g_off[w + 1];

    float4 acc = make_float4(0.f, 0.f, 0.f, 0.f);
    for (int j = beg; j < end; j++) {
        const int4 ed = g_edges[j];                         // warp-broadcast
        const float sc = isMiu ? __int_as_float(ed.y) : __int_as_float(ed.z);
        const float4* base = isMiu ? (const float4*)(g_miu + (size_t)ed.x * OUT_F)
                                   : (const float4*)(g_sig + (size_t)ed.x * OUT_F);
        const float4 v = base[c];
        acc.x = fmaf(v.x, sc, acc.x);
        acc.y = fmaf(v.y, sc, acc.y);
        acc.z = fmaf(v.z, sc, acc.z);
        acc.w = fmaf(v.w, sc, acc.w);
    }

    float* dstb = isMiu ? out + (size_t)w * OUT_F
                        : out + ((size_t)N_NODES + w) * OUT_F;
    ((float4*)dstb)[c] = acc;
}

// ---------------------------------------------------------------------------
// Inputs: features, edge_src, edge_dst, adj1_vals, adj2_vals, weight_miu,
//         weight_sigma. Output: [miu_out ; sigma_out] row-major.
// ---------------------------------------------------------------------------
extern "C" void kernel_launch(void* const* d_in, const int* in_sizes, int n_in,
                              void* d_out, int out_size)
{
    const float* feat = (const float*)d_in[0];
    const void*  esrc = d_in[1];
    const void*  edst = d_in[2];
    const float* a1   = (const float*)d_in[3];
    const float* a2   = (const float*)d_in[4];
    const float* wm   = (const float*)d_in[5];
    const float* ws   = (const float*)d_in[6];
    float*       out  = (float*)d_out;
    const int E = in_sizes[3];

    probe_kernel<<<1, 1>>>(esrc);
    zero_kernel<<<(N_NODES + 255) / 256, 256>>>();
    hist_kernel<<<(E + 255) / 256, 256>>>(edst, E);
    scan_kernel<<<1, SCAN_T>>>();
    fill_kernel<<<(E + 255) / 256, 256>>>(esrc, edst, a1, a2, E);

    gemm_act_kernel<<<(N_NODES + ROWS_PER_BLK - 1) / ROWS_PER_BLK, 256>>>(feat, wm, ws);

    const long long threads = (long long)N_NODES * 32;
    gather_kernel<<<(int)((threads + 255) / 256), 256>>>(out);
}

// round 8
// speedup vs baseline: 1.4093x; 1.4093x over previous
#include <cuda_runtime.h>

#define N_NODES 50000
#define IN_F    256
#define OUT_F   64
#define ROWS_PER_BLK 32
#define MAX_E   800000
#define SCAN_B  ((N_NODES + 255) / 256)   // 196 blocks

// ---- __device__ scratch (alloc-guard-safe) ----
__device__ __align__(16) float g_miu[N_NODES * OUT_F];   // miu*att
__device__ __align__(16) float g_sig[N_NODES * OUT_F];   // sigma*att^2
__device__ int  g_cnt[N_NODES];          // per-dst degree
__device__ int  g_off[N_NODES + 1];      // CSR row offsets
__device__ int  g_cur[N_NODES];          // fill cursors
__device__ int  g_bsum[SCAN_B];          // per-block partial sums
__device__ __align__(16) int4 g_edges[MAX_E];  // {src, a1_bits, a2_bits, pad}
__device__ int  g_is64;

// ---------------------------------------------------------------------------
// Dtype probe: reference declares int64 indices but default-JAX downgrades to
// int32. 32 consecutive int64 reads all landing in [0,N) only if truly int64.
// ---------------------------------------------------------------------------
__global__ void probe_kernel(const void* __restrict__ esrc)
{
    const long long* p = (const long long*)esrc;
    int ok64 = 1;
    for (int i = 0; i < 32; i++) {
        long long v = p[i];
        if (v < 0 || v >= N_NODES) { ok64 = 0; break; }
    }
    g_is64 = ok64;
}

__device__ __forceinline__ int load_idx(const void* p, int i, int is64)
{
    return is64 ? (int)((const long long*)p)[i] : ((const int*)p)[i];
}

// ---- CSR build ----
__global__ __launch_bounds__(256) void zero_kernel()
{
    const int i = blockIdx.x * 256 + threadIdx.x;
    if (i < N_NODES) g_cnt[i] = 0;
}

__global__ __launch_bounds__(256) void hist_kernel(const void* __restrict__ edst, int E)
{
    const int i = blockIdx.x * 256 + threadIdx.x;
    if (i >= E) return;
    const int d = load_idx(edst, i, g_is64);
    if ((unsigned)d < N_NODES) atomicAdd(&g_cnt[d], 1);
}

// Pass 1: per-block exclusive scan (256 elems/block) + block total.
__global__ __launch_bounds__(256) void scan1_kernel()
{
    __shared__ int wsum[8];
    const int tid  = threadIdx.x;
    const int lane = tid & 31;
    const int wid  = tid >> 5;
    const int i    = blockIdx.x * 256 + tid;

    const int val = (i < N_NODES) ? g_cnt[i] : 0;

    // warp inclusive scan
    int v = val;
#pragma unroll
    for (int o = 1; o < 32; o <<= 1) {
        const int n = __shfl_up_sync(0xffffffffu, v, o);
        if (lane >= o) v += n;
    }
    if (lane == 31) wsum[wid] = v;
    __syncthreads();

    if (wid == 0) {
        int w = (lane < 8) ? wsum[lane] : 0;
#pragma unroll
        for (int o = 1; o < 8; o <<= 1) {
            const int n = __shfl_up_sync(0xffffffffu, w, o);
            if (lane >= o) w += n;
        }
        if (lane < 8) wsum[lane] = w;   // inclusive warp totals
    }
    __syncthreads();

    const int warp_base = (wid > 0) ? wsum[wid - 1] : 0;
    if (i < N_NODES) g_off[i] = warp_base + v - val;   // block-local exclusive
    if (tid == 255) g_bsum[blockIdx.x] = wsum[7];      // block total
}

// Pass 2: one block scans the 196 block totals (exclusive), writes g_off[N].
__global__ __launch_bounds__(256) void scan2_kernel()
{
    __shared__ int wsum[8];
    const int tid  = threadIdx.x;
    const int lane = tid & 31;
    const int wid  = tid >> 5;

    const int val = (tid < SCAN_B) ? g_bsum[tid] : 0;
    int v = val;
#pragma unroll
    for (int o = 1; o < 32; o <<= 1) {
        const int n = __shfl_up_sync(0xffffffffu, v, o);
        if (lane >= o) v += n;
    }
    if (lane == 31) wsum[wid] = v;
    __syncthreads();
    if (wid == 0) {
        int w = (lane < 8) ? wsum[lane] : 0;
#pragma unroll
        for (int o = 1; o < 8; o <<= 1) {
            const int n = __shfl_up_sync(0xffffffffu, w, o);
            if (lane >= o) w += n;
        }
        if (lane < 8) wsum[lane] = w;
    }
    __syncthreads();
    const int warp_base = (wid > 0) ? wsum[wid - 1] : 0;
    if (tid < SCAN_B) g_bsum[tid] = warp_base + v - val;   // exclusive
    if (tid == 255) g_off[N_NODES] = wsum[7];              // grand total
}

// Pass 3: add block bases; init cursors.
__global__ __launch_bounds__(256) void scan3_kernel()
{
    const int i = blockIdx.x * 256 + threadIdx.x;
    if (i >= N_NODES) return;
    const int o = g_off[i] + g_bsum[blockIdx.x];
    g_off[i] = o;
    g_cur[i] = o;
}

__global__ __launch_bounds__(256) void fill_kernel(
    const void* __restrict__ esrc, const void* __restrict__ edst,
    const float* __restrict__ a1, const float* __restrict__ a2, int E)
{
    const int i = blockIdx.x * 256 + threadIdx.x;
    if (i >= E) return;
    const int is64 = g_is64;
    const int s = load_idx(esrc, i, is64);
    const int d = load_idx(edst, i, is64);
    if ((unsigned)s >= N_NODES || (unsigned)d >= N_NODES) return;
    const int pos = atomicAdd(&g_cur[d], 1);
    g_edges[pos] = make_int4(s, __float_as_int(__ldg(a1 + i)),
                                __float_as_int(__ldg(a2 + i)), 0);
}

// ---------------------------------------------------------------------------
// Kernel A: fused dual-GEMM + activations (FFMA roofline ~100us).
// ---------------------------------------------------------------------------
__global__ __launch_bounds__(256) void gemm_act_kernel(
    const float* __restrict__ feat,
    const float* __restrict__ wm,
    const float* __restrict__ ws)
{
    __shared__ float fs[ROWS_PER_BLK * IN_F];
    const int row0 = blockIdx.x * ROWS_PER_BLK;
    const int tid  = threadIdx.x;
    const int nrows = min(ROWS_PER_BLK, N_NODES - row0);

    {
        const float4* gf  = (const float4*)(feat + (size_t)row0 * IN_F);
        float4*       fs4 = (float4*)fs;
        const int total4  = nrows * (IN_F / 4);
        for (int i = tid; i < total4; i += 256) fs4[i] = gf[i];
    }
    __syncthreads();

    const int f  = tid & 63;
    const int rg = tid >> 6;

    float accm[8], accs[8];
#pragma unroll
    for (int r = 0; r < 8; r++) { accm[r] = 0.f; accs[r] = 0.f; }

    const float4* fs4 = (const float4*)fs;

    for (int k = 0; k < IN_F; k += 4) {
        const float wm0 = __ldg(&wm[(k + 0) * OUT_F + f]);
        const float wm1 = __ldg(&wm[(k + 1) * OUT_F + f]);
        const float wm2 = __ldg(&wm[(k + 2) * OUT_F + f]);
        const float wm3 = __ldg(&wm[(k + 3) * OUT_F + f]);
        const float ws0 = __ldg(&ws[(k + 0) * OUT_F + f]);
        const float ws1 = __ldg(&ws[(k + 1) * OUT_F + f]);
        const float ws2 = __ldg(&ws[(k + 2) * OUT_F + f]);
        const float ws3 = __ldg(&ws[(k + 3) * OUT_F + f]);
#pragma unroll
        for (int r = 0; r < 8; r++) {
            const float4 fv = fs4[(rg * 8 + r) * (IN_F / 4) + (k >> 2)];
            accm[r] = fmaf(fv.x, wm0, fmaf(fv.y, wm1, fmaf(fv.z, wm2, fmaf(fv.w, wm3, accm[r]))));
            accs[r] = fmaf(fv.x, ws0, fmaf(fv.y, ws1, fmaf(fv.z, ws2, fmaf(fv.w, ws3, accs[r]))));
        }
    }

#pragma unroll
    for (int r = 0; r < 8; r++) {
        const int row = row0 + rg * 8 + r;
        if (row < N_NODES) {
            const float m   = accm[r];
            const float mi  = (m > 0.f) ? m : (expf(m) - 1.f);   // ELU
            const float s   = (accs[r] > 0.f) ? accs[r] : 0.f;   // ReLU
            const float att = expf(-s);                          // GAMMA=1
            g_miu[row * OUT_F + f] = mi * att;
            g_sig[row * OUT_F + f] = s * att * att;
        }
    }
}

// ---------------------------------------------------------------------------
// Kernel B: CSR gather — one warp per dst node, zero atomics.
//   lanes 0..15  accumulate the 16 float4 chunks of miu_out[d]
//   lanes 16..31 accumulate the 16 float4 chunks of sigma_out[d]
// Writes every output element -> no output memset needed.
// ---------------------------------------------------------------------------
__global__ __launch_bounds__(256) void gather_kernel(float* __restrict__ out)
{
    const int w = (blockIdx.x * 256 + threadIdx.x) >> 5;   // dst node
    if (w >= N_NODES) return;
    const int lane   = threadIdx.x & 31;
    const int c      = lane & 15;
    const bool isMiu = lane < 16;

    const int beg = g_off[w];
    const int end = g_off[w + 1];

    float4 acc = make_float4(0.f, 0.f, 0.f, 0.f);
    for (int j = beg; j < end; j++) {
        const int4 ed = g_edges[j];                         // warp-broadcast
        const float sc = isMiu ? __int_as_float(ed.y) : __int_as_float(ed.z);
        const float4* base = isMiu ? (const float4*)(g_miu + (size_t)ed.x * OUT_F)
                                   : (const float4*)(g_sig + (size_t)ed.x * OUT_F);
        const float4 v = base[c];
        acc.x = fmaf(v.x, sc, acc.x);
        acc.y = fmaf(v.y, sc, acc.y);
        acc.z = fmaf(v.z, sc, acc.z);
        acc.w = fmaf(v.w, sc, acc.w);
    }

    float* dstb = isMiu ? out + (size_t)w * OUT_F
                        : out + ((size_t)N_NODES + w) * OUT_F;
    ((float4*)dstb)[c] = acc;
}

// ---------------------------------------------------------------------------
// Inputs: features, edge_src, edge_dst, adj1_vals, adj2_vals, weight_miu,
//         weight_sigma. Output: [miu_out ; sigma_out] row-major.
// ---------------------------------------------------------------------------
extern "C" void kernel_launch(void* const* d_in, const int* in_sizes, int n_in,
                              void* d_out, int out_size)
{
    const float* feat = (const float*)d_in[0];
    const void*  esrc = d_in[1];
    const void*  edst = d_in[2];
    const float* a1   = (const float*)d_in[3];
    const float* a2   = (const float*)d_in[4];
    const float* wm   = (const float*)d_in[5];
    const float* ws   = (const float*)d_in[6];
    float*       out  = (float*)d_out;
    const int E = in_sizes[3];

    probe_kernel<<<1, 1>>>(esrc);
    zero_kernel<<<SCAN_B, 256>>>();
    hist_kernel<<<(E + 255) / 256, 256>>>(edst, E);
    scan1_kernel<<<SCAN_B, 256>>>();
    scan2_kernel<<<1, 256>>>();
    scan3_kernel<<<SCAN_B, 256>>>();
    fill_kernel<<<(E + 255) / 256, 256>>>(esrc, edst, a1, a2, E);

    gemm_act_kernel<<<(N_NODES + ROWS_PER_BLK - 1) / ROWS_PER_BLK, 256>>>(feat, wm, ws);

    const long long threads = (long long)N_NODES * 32;
    gather_kernel<<<(int)((threads + 255) / 256), 256>>>(out);
}

// round 10
// speedup vs baseline: 2.0315x; 1.4415x over previous
#include <cuda_runtime.h>
#include <cuda_bf16.h>
#include <cstdint>

#define N_NODES 50000
#define IN_F    256
#define OUT_F   64
#define MAX_E   800000
#define SCAN_B  ((N_NODES + 255) / 256)   // 196
#define TILE_M  128
#define GEMM_BLOCKS ((N_NODES + TILE_M - 1) / TILE_M)  // 391

// smem pitch: 72 bf16 = 144B = 36 banks -> fragment loads conflict-free
#define APITCH 72
// dynamic smem: A_hi[128][72] + A_lo[128][72] + B[4][64][72]  (bf16)
#define SM_A_HI 0
#define SM_A_LO (128 * APITCH)
#define SM_B    (2 * 128 * APITCH)
#define SM_ELEMS (SM_B + 4 * 64 * APITCH)
#define SM_BYTES (SM_ELEMS * 2)          // 73728 B

// ---- __device__ scratch (alloc-guard-safe) ----
__device__ __align__(16) float g_miu[N_NODES * OUT_F];   // miu*att
__device__ __align__(16) float g_sig[N_NODES * OUT_F];   // sigma*att^2
__device__ int  g_cnt[N_NODES];
__device__ int  g_off[N_NODES + 1];
__device__ int  g_cur[N_NODES];
__device__ int  g_bsum[SCAN_B];
__device__ __align__(16) int4 g_edges[MAX_E];
__device__ int  g_is64;
// weight fragments, k-contiguous [n][k]: [0]=Wm_hi [1]=Wm_lo [2]=Ws_hi [3]=Ws_lo
__device__ __align__(16) __nv_bfloat16 g_wfrag[4][OUT_F * IN_F];

// =================== dtype probe + CSR build (validated) ===================
__global__ void probe_kernel(const void* __restrict__ esrc)
{
    const long long* p = (const long long*)esrc;
    int ok64 = 1;
    for (int i = 0; i < 32; i++) {
        long long v = p[i];
        if (v < 0 || v >= N_NODES) { ok64 = 0; break; }
    }
    g_is64 = ok64;
}
__device__ __forceinline__ int load_idx(const void* p, int i, int is64)
{ return is64 ? (int)((const long long*)p)[i] : ((const int*)p)[i]; }

__global__ __launch_bounds__(256) void zero_kernel()
{
    const int i = blockIdx.x * 256 + threadIdx.x;
    if (i < N_NODES) g_cnt[i] = 0;
}
__global__ __launch_bounds__(256) void hist_kernel(const void* __restrict__ edst, int E)
{
    const int i = blockIdx.x * 256 + threadIdx.x;
    if (i >= E) return;
    const int d = load_idx(edst, i, g_is64);
    if ((unsigned)d < N_NODES) atomicAdd(&g_cnt[d], 1);
}
__global__ __launch_bounds__(256) void scan1_kernel()
{
    __shared__ int wsum[8];
    const int tid = threadIdx.x, lane = tid & 31, wid = tid >> 5;
    const int i = blockIdx.x * 256 + tid;
    const int val = (i < N_NODES) ? g_cnt[i] : 0;
    int v = val;
#pragma unroll
    for (int o = 1; o < 32; o <<= 1) { int n = __shfl_up_sync(~0u, v, o); if (lane >= o) v += n; }
    if (lane == 31) wsum[wid] = v;
    __syncthreads();
    if (wid == 0) {
        int w = (lane < 8) ? wsum[lane] : 0;
#pragma unroll
        for (int o = 1; o < 8; o <<= 1) { int n = __shfl_up_sync(~0u, w, o); if (lane >= o) w += n; }
        if (lane < 8) wsum[lane] = w;
    }
    __syncthreads();
    const int wb = (wid > 0) ? wsum[wid - 1] : 0;
    if (i < N_NODES) g_off[i] = wb + v - val;
    if (tid == 255) g_bsum[blockIdx.x] = wsum[7];
}
__global__ __launch_bounds__(256) void scan2_kernel()
{
    __shared__ int wsum[8];
    const int tid = threadIdx.x, lane = tid & 31, wid = tid >> 5;
    const int val = (tid < SCAN_B) ? g_bsum[tid] : 0;
    int v = val;
#pragma unroll
    for (int o = 1; o < 32; o <<= 1) { int n = __shfl_up_sync(~0u, v, o); if (lane >= o) v += n; }
    if (lane == 31) wsum[wid] = v;
    __syncthreads();
    if (wid == 0) {
        int w = (lane < 8) ? wsum[lane] : 0;
#pragma unroll
        for (int o = 1; o < 8; o <<= 1) { int n = __shfl_up_sync(~0u, w, o); if (lane >= o) w += n; }
        if (lane < 8) wsum[lane] = w;
    }
    __syncthreads();
    const int wb = (wid > 0) ? wsum[wid - 1] : 0;
    if (tid < SCAN_B) g_bsum[tid] = wb + v - val;
    if (tid == 255) g_off[N_NODES] = wsum[7];
}
__global__ __launch_bounds__(256) void scan3_kernel()
{
    const int i = blockIdx.x * 256 + threadIdx.x;
    if (i >= N_NODES) return;
    const int o = g_off[i] + g_bsum[blockIdx.x];
    g_off[i] = o;
    g_cur[i] = o;
}
__global__ __launch_bounds__(256) void fill_kernel(
    const void* __restrict__ esrc, const void* __restrict__ edst,
    const float* __restrict__ a1, const float* __restrict__ a2, int E)
{
    const int i = blockIdx.x * 256 + threadIdx.x;
    if (i >= E) return;
    const int is64 = g_is64;
    const int s = load_idx(esrc, i, is64);
    const int d = load_idx(edst, i, is64);
    if ((unsigned)s >= N_NODES || (unsigned)d >= N_NODES) return;
    const int pos = atomicAdd(&g_cur[d], 1);
    g_edges[pos] = make_int4(s, __float_as_int(__ldg(a1 + i)),
                                __float_as_int(__ldg(a2 + i)), 0);
}

// ===== weight prep: W[k][n] f32 -> hi/lo bf16 in [n][k] k-contiguous layout =====
__global__ __launch_bounds__(256) void prep_w_kernel(
    const float* __restrict__ wm, const float* __restrict__ ws)
{
    const int i = blockIdx.x * 256 + threadIdx.x;   // 2*64*256 = 32768
    if (i >= 2 * OUT_F * IN_F) return;
    const int mat = i >> 14;
    const int r   = i & 16383;
    const int n   = r >> 8;
    const int k   = r & 255;
    const float v = (mat ? ws : wm)[k * OUT_F + n];
    const __nv_bfloat16 h = __float2bfloat16(v);
    const __nv_bfloat16 l = __float2bfloat16(v - __bfloat162float(h));
    g_wfrag[mat * 2 + 0][n * IN_F + k] = h;
    g_wfrag[mat * 2 + 1][n * IN_F + k] = l;
}

// =================== mma.sync dual-GEMM + activations ===================
// m16n8k16 bf16 HMMA, fp32 accum, 3-term hi/lo split for fp32-level accuracy.
// Warp w owns rows [16w,16w+16); 8 n-tiles cover N=64; K in 4 smem chunks of 64.
__device__ __forceinline__ void mma16816(float* c, const uint32_t* a,
                                         uint32_t b0, uint32_t b1)
{
    asm volatile(
        "mma.sync.aligned.m16n8k16.row.col.f32.bf16.bf16.f32 "
        "{%0,%1,%2,%3}, {%4,%5,%6,%7}, {%8,%9}, {%0,%1,%2,%3};"
        : "+f"(c[0]), "+f"(c[1]), "+f"(c[2]), "+f"(c[3])
        : "r"(a[0]), "r"(a[1]), "r"(a[2]), "r"(a[3]), "r"(b0), "r"(b1));
}

__global__ __launch_bounds__(256, 2) void gemm_mma_kernel(const float* __restrict__ feat)
{
    extern __shared__ __nv_bfloat16 sm[];
    __nv_bfloat16* Ah = sm + SM_A_HI;
    __nv_bfloat16* Al = sm + SM_A_LO;
    __nv_bfloat16* Bs = sm + SM_B;          // [buf][64][APITCH], buf = mat*2+hl

    const int tid  = threadIdx.x;
    const int wid  = tid >> 5;
    const int lane = tid & 31;
    const int gid  = lane >> 2;             // 0..7
    const int tq   = lane & 3;              // 0..3
    const int row0 = blockIdx.x * TILE_M;
    const int nrows = min(TILE_M, N_NODES - row0);
    const int wr   = wid * 16;              // warp row base in tile

    float accM[8][4], accS[8][4];
#pragma unroll
    for (int t = 0; t < 8; t++)
#pragma unroll
        for (int j = 0; j < 4; j++) { accM[t][j] = 0.f; accS[t][j] = 0.f; }

    for (int kc = 0; kc < 4; kc++) {
        // ---- stage A chunk: 128 rows x 64 k, f32 -> bf16 hi/lo ----
        {
            const float4* gf = (const float4*)(feat + (size_t)row0 * IN_F);
#pragma unroll
            for (int it = 0; it < 8; it++) {
                const int e  = tid + it * 256;       // 0..2047
                const int r  = e >> 4;
                const int kg = e & 15;               // float4 group in chunk
                __nv_bfloat162 hp[2], lp[2];
                if (r < nrows) {
                    const float4 f = gf[r * 64 + kc * 16 + kg];
                    const __nv_bfloat16 h0 = __float2bfloat16(f.x);
                    const __nv_bfloat16 h1 = __float2bfloat16(f.y);
                    const __nv_bfloat16 h2 = __float2bfloat16(f.z);
                    const __nv_bfloat16 h3 = __float2bfloat16(f.w);
                    hp[0] = __nv_bfloat162(h0, h1); hp[1] = __nv_bfloat162(h2, h3);
                    lp[0] = __nv_bfloat162(__float2bfloat16(f.x - __bfloat162float(h0)),
                                           __float2bfloat16(f.y - __bfloat162float(h1)));
                    lp[1] = __nv_bfloat162(__float2bfloat16(f.z - __bfloat162float(h2)),
                                           __float2bfloat16(f.w - __bfloat162float(h3)));
                } else {
                    hp[0] = hp[1] = lp[0] = lp[1] = __nv_bfloat162(__nv_bfloat16(0.f), __nv_bfloat16(0.f));
                }
                *(uint2*)(Ah + r * APITCH + kg * 4) = *(uint2*)hp;
                *(uint2*)(Al + r * APITCH + kg * 4) = *(uint2*)lp;
            }
        }
        // ---- stage B chunk: 4 buffers x 64 n x 64 k ----
#pragma unroll
        for (int it = 0; it < 16; it++) {
            const int e   = tid + it * 256;          // 0..4095 uint2 (4 bf16)
            const int buf = e >> 10;
            const int r   = (e >> 4) & 63;
            const int kg  = e & 15;
            *(uint2*)(Bs + (buf * 64 + r) * APITCH + kg * 4) =
                *(const uint2*)(&g_wfrag[buf][r * IN_F + kc * 64 + kg * 4]);
        }
        __syncthreads();

        // ---- compute: 4 k-steps of 16 ----
#pragma unroll
        for (int ks = 0; ks < 4; ks++) {
            const int k0 = ks * 16 + tq * 2;
            uint32_t ah[4], al[4];
            const __nv_bfloat16* ar = Ah + (wr + gid) * APITCH;
            ah[0] = *(const uint32_t*)(ar + k0);
            ah[1] = *(const uint32_t*)(ar + 8 * APITCH + k0);
            ah[2] = *(const uint32_t*)(ar + k0 + 8);
            ah[3] = *(const uint32_t*)(ar + 8 * APITCH + k0 + 8);
            const __nv_bfloat16* arl = Al + (wr + gid) * APITCH;
            al[0] = *(const uint32_t*)(arl + k0);
            al[1] = *(const uint32_t*)(arl + 8 * APITCH + k0);
            al[2] = *(const uint32_t*)(arl + k0 + 8);
            al[3] = *(const uint32_t*)(arl + 8 * APITCH + k0 + 8);

#pragma unroll
            for (int nt = 0; nt < 8; nt++) {
                const int n = nt * 8 + gid;
                const __nv_bfloat16* b0p = Bs + n * APITCH;            // Wm_hi
                const __nv_bfloat16* b1p = Bs + (64 + n) * APITCH;     // Wm_lo
                const __nv_bfloat16* b2p = Bs + (128 + n) * APITCH;    // Ws_hi
                const __nv_bfloat16* b3p = Bs + (192 + n) * APITCH;    // Ws_lo
                const uint32_t mh0 = *(const uint32_t*)(b0p + k0);
                const uint32_t mh1 = *(const uint32_t*)(b0p + k0 + 8);
                const uint32_t ml0 = *(const uint32_t*)(b1p + k0);
                const uint32_t ml1 = *(const uint32_t*)(b1p + k0 + 8);
                const uint32_t sh0 = *(const uint32_t*)(b2p + k0);
                const uint32_t sh1 = *(const uint32_t*)(b2p + k0 + 8);
                const uint32_t sl0 = *(const uint32_t*)(b3p + k0);
                const uint32_t sl1 = *(const uint32_t*)(b3p + k0 + 8);
                mma16816(accM[nt], ah, mh0, mh1);
                mma16816(accM[nt], al, mh0, mh1);
                mma16816(accM[nt], ah, ml0, ml1);
                mma16816(accS[nt], ah, sh0, sh1);
                mma16816(accS[nt], al, sh0, sh1);
                mma16816(accS[nt], ah, sl0, sl1);
            }
        }
        __syncthreads();
    }

    // ---- epilogue: lane-local activations, write message scratch ----
#pragma unroll
    for (int t = 0; t < 8; t++) {
        const int n = t * 8 + tq * 2;
#pragma unroll
        for (int h = 0; h < 2; h++) {
            const int row = row0 + wr + gid + h * 8;
            if (row < N_NODES) {
                const float s0 = fmaxf(accS[t][2 * h + 0], 0.f);
                const float s1 = fmaxf(accS[t][2 * h + 1], 0.f);
                const float a0 = expf(-s0), a1 = expf(-s1);
                const float m0 = accM[t][2 * h + 0];
                const float m1 = accM[t][2 * h + 1];
                const float mi0 = (m0 > 0.f) ? m0 : (expf(m0) - 1.f);
                const float mi1 = (m1 > 0.f) ? m1 : (expf(m1) - 1.f);
                *(float2*)(g_sig + (size_t)row * OUT_F + n) =
                    make_float2(s0 * a0 * a0, s1 * a1 * a1);
                *(float2*)(g_miu + (size_t)row * OUT_F + n) =
                    make_float2(mi0 * a0, mi1 * a1);
            }
        }
    }
}

// =================== CSR gather (validated) ===================
__global__ __launch_bounds__(256) void gather_kernel(float* __restrict__ out)
{
    const int w = (blockIdx.x * 256 + threadIdx.x) >> 5;
    if (w >= N_NODES) return;
    const int lane   = threadIdx.x & 31;
    const int c      = lane & 15;
    const bool isMiu = lane < 16;

    const int beg = g_off[w];
    const int end = g_off[w + 1];

    float4 acc = make_float4(0.f, 0.f, 0.f, 0.f);
    for (int j = beg; j < end; j++) {
        const int4 ed = g_edges[j];
        const float sc = isMiu ? __int_as_float(ed.y) : __int_as_float(ed.z);
        const float4* base = isMiu ? (const float4*)(g_miu + (size_t)ed.x * OUT_F)
                                   : (const float4*)(g_sig + (size_t)ed.x * OUT_F);
        const float4 v = base[c];
        acc.x = fmaf(v.x, sc, acc.x);
        acc.y = fmaf(v.y, sc, acc.y);
        acc.z = fmaf(v.z, sc, acc.z);
        acc.w = fmaf(v.w, sc, acc.w);
    }

    float* dstb = isMiu ? out + (size_t)w * OUT_F
                        : out + ((size_t)N_NODES + w) * OUT_F;
    ((float4*)dstb)[c] = acc;
}

// =================== launch ===================
extern "C" void kernel_launch(void* const* d_in, const int* in_sizes, int n_in,
                              void* d_out, int out_size)
{
    const float* feat = (const float*)d_in[0];
    const void*  esrc = d_in[1];
    const void*  edst = d_in[2];
    const float* a1   = (const float*)d_in[3];
    const float* a2   = (const float*)d_in[4];
    const float* wm   = (const float*)d_in[5];
    const float* ws   = (const float*)d_in[6];
    float*       out  = (float*)d_out;
    const int E = in_sizes[3];

    static int smem_set = 0;
    if (!smem_set) {
        cudaFuncSetAttribute(gemm_mma_kernel,
                             cudaFuncAttributeMaxDynamicSharedMemorySize, SM_BYTES);
        smem_set = 1;
    }

    probe_kernel<<<1, 1>>>(esrc);
    zero_kernel<<<SCAN_B, 256>>>();
    hist_kernel<<<(E + 255) / 256, 256>>>(edst, E);
    scan1_kernel<<<SCAN_B, 256>>>();
    scan2_kernel<<<1, 256>>>();
    scan3_kernel<<<SCAN_B, 256>>>();
    fill_kernel<<<(E + 255) / 256, 256>>>(esrc, edst, a1, a2, E);

    prep_w_kernel<<<128, 256>>>(wm, ws);
    gemm_mma_kernel<<<GEMM_BLOCKS, 256, SM_BYTES>>>(feat);

    const long long threads = (long long)N_NODES * 32;
    gather_kernel<<<(int)((threads + 255) / 256), 256>>>(out);
}

// round 11
// speedup vs baseline: 2.3368x; 1.1503x over previous
#include <cuda_runtime.h>
#include <cuda_bf16.h>
#include <cstdint>

#define N_NODES 50000
#define IN_F    256
#define OUT_F   64
#define MAX_E   800000
#define SCAN_B  ((N_NODES + 255) / 256)   // 196
#define TILE_M  128
#define GEMM_BLOCKS ((N_NODES + TILE_M - 1) / TILE_M)  // 391

// smem pitch: 72 bf16 = 144B = 36 banks -> fragment loads conflict-free
#define APITCH 72
#define SM_A_HI 0
#define SM_A_LO (128 * APITCH)
#define SM_B    (2 * 128 * APITCH)
#define SM_ELEMS (SM_B + 4 * 64 * APITCH)
#define SM_BYTES (SM_ELEMS * 2)          // 73728 B

// ---- __device__ scratch (alloc-guard-safe) ----
// interleaved messages: [node][0..63]=miu*att, [node][64..127]=sigma*att^2
__device__ __align__(16) float g_msg[N_NODES * 128];
__device__ int  g_cnt[N_NODES];
__device__ int  g_off[N_NODES + 1];
__device__ int  g_cur[N_NODES];
__device__ int  g_bsum[SCAN_B];
__device__ __align__(16) int4 g_edges[MAX_E];
__device__ int  g_is64;
// weight fragments, k-contiguous [n][k]: [0]=Wm_hi [1]=Wm_lo [2]=Ws_hi [3]=Ws_lo
__device__ __align__(16) __nv_bfloat16 g_wfrag[4][OUT_F * IN_F];

// =================== dtype probe + CSR build (validated) ===================
__global__ void probe_kernel(const void* __restrict__ esrc)
{
    const long long* p = (const long long*)esrc;
    int ok64 = 1;
    for (int i = 0; i < 32; i++) {
        long long v = p[i];
        if (v < 0 || v >= N_NODES) { ok64 = 0; break; }
    }
    g_is64 = ok64;
}
__device__ __forceinline__ int load_idx(const void* p, int i, int is64)
{ return is64 ? (int)((const long long*)p)[i] : ((const int*)p)[i]; }

__global__ __launch_bounds__(256) void zero_kernel()
{
    const int i = blockIdx.x * 256 + threadIdx.x;
    if (i < N_NODES) g_cnt[i] = 0;
}
__global__ __launch_bounds__(256) void hist_kernel(const void* __restrict__ edst, int E)
{
    const int i = blockIdx.x * 256 + threadIdx.x;
    if (i >= E) return;
    const int d = load_idx(edst, i, g_is64);
    if ((unsigned)d < N_NODES) atomicAdd(&g_cnt[d], 1);
}
__global__ __launch_bounds__(256) void scan1_kernel()
{
    __shared__ int wsum[8];
    const int tid = threadIdx.x, lane = tid & 31, wid = tid >> 5;
    const int i = blockIdx.x * 256 + tid;
    const int val = (i < N_NODES) ? g_cnt[i] : 0;
    int v = val;
#pragma unroll
    for (int o = 1; o < 32; o <<= 1) { int n = __shfl_up_sync(~0u, v, o); if (lane >= o) v += n; }
    if (lane == 31) wsum[wid] = v;
    __syncthreads();
    if (wid == 0) {
        int w = (lane < 8) ? wsum[lane] : 0;
#pragma unroll
        for (int o = 1; o < 8; o <<= 1) { int n = __shfl_up_sync(~0u, w, o); if (lane >= o) w += n; }
        if (lane < 8) wsum[lane] = w;
    }
    __syncthreads();
    const int wb = (wid > 0) ? wsum[wid - 1] : 0;
    if (i < N_NODES) g_off[i] = wb + v - val;
    if (tid == 255) g_bsum[blockIdx.x] = wsum[7];
}
__global__ __launch_bounds__(256) void scan2_kernel()
{
    __shared__ int wsum[8];
    const int tid = threadIdx.x, lane = tid & 31, wid = tid >> 5;
    const int val = (tid < SCAN_B) ? g_bsum[tid] : 0;
    int v = val;
#pragma unroll
    for (int o = 1; o < 32; o <<= 1) { int n = __shfl_up_sync(~0u, v, o); if (lane >= o) v += n; }
    if (lane == 31) wsum[wid] = v;
    __syncthreads();
    if (wid == 0) {
        int w = (lane < 8) ? wsum[lane] : 0;
#pragma unroll
        for (int o = 1; o < 8; o <<= 1) { int n = __shfl_up_sync(~0u, w, o); if (lane >= o) w += n; }
        if (lane < 8) wsum[lane] = w;
    }
    __syncthreads();
    const int wb = (wid > 0) ? wsum[wid - 1] : 0;
    if (tid < SCAN_B) g_bsum[tid] = wb + v - val;
    if (tid == 255) g_off[N_NODES] = wsum[7];
}
__global__ __launch_bounds__(256) void scan3_kernel()
{
    const int i = blockIdx.x * 256 + threadIdx.x;
    if (i >= N_NODES) return;
    const int o = g_off[i] + g_bsum[blockIdx.x];
    g_off[i] = o;
    g_cur[i] = o;
}
__global__ __launch_bounds__(256) void fill_kernel(
    const void* __restrict__ esrc, const void* __restrict__ edst,
    const float* __restrict__ a1, const float* __restrict__ a2, int E)
{
    const int i = blockIdx.x * 256 + threadIdx.x;
    if (i >= E) return;
    const int is64 = g_is64;
    const int s = load_idx(esrc, i, is64);
    const int d = load_idx(edst, i, is64);
    if ((unsigned)s >= N_NODES || (unsigned)d >= N_NODES) return;
    const int pos = atomicAdd(&g_cur[d], 1);
    g_edges[pos] = make_int4(s, __float_as_int(__ldg(a1 + i)),
                                __float_as_int(__ldg(a2 + i)), 0);
}

// ===== weight prep: W[k][n] f32 -> hi/lo bf16 in [n][k] k-contiguous layout =====
__global__ __launch_bounds__(256) void prep_w_kernel(
    const float* __restrict__ wm, const float* __restrict__ ws)
{
    const int i = blockIdx.x * 256 + threadIdx.x;   // 32768
    if (i >= 2 * OUT_F * IN_F) return;
    const int mat = i >> 14;
    const int r   = i & 16383;
    const int n   = r >> 8;
    const int k   = r & 255;
    const float v = (mat ? ws : wm)[k * OUT_F + n];
    const __nv_bfloat16 h = __float2bfloat16(v);
    const __nv_bfloat16 l = __float2bfloat16(v - __bfloat162float(h));
    g_wfrag[mat * 2 + 0][n * IN_F + k] = h;
    g_wfrag[mat * 2 + 1][n * IN_F + k] = l;
}

// =================== mma.sync dual-GEMM + activations (validated R10) ========
__device__ __forceinline__ void mma16816(float* c, const uint32_t* a,
                                         uint32_t b0, uint32_t b1)
{
    asm volatile(
        "mma.sync.aligned.m16n8k16.row.col.f32.bf16.bf16.f32 "
        "{%0,%1,%2,%3}, {%4,%5,%6,%7}, {%8,%9}, {%0,%1,%2,%3};"
        : "+f"(c[0]), "+f"(c[1]), "+f"(c[2]), "+f"(c[3])
        : "r"(a[0]), "r"(a[1]), "r"(a[2]), "r"(a[3]), "r"(b0), "r"(b1));
}

__global__ __launch_bounds__(256, 2) void gemm_mma_kernel(const float* __restrict__ feat)
{
    extern __shared__ __nv_bfloat16 sm[];
    __nv_bfloat16* Ah = sm + SM_A_HI;
    __nv_bfloat16* Al = sm + SM_A_LO;
    __nv_bfloat16* Bs = sm + SM_B;

    const int tid  = threadIdx.x;
    const int wid  = tid >> 5;
    const int lane = tid & 31;
    const int gid  = lane >> 2;
    const int tq   = lane & 3;
    const int row0 = blockIdx.x * TILE_M;
    const int nrows = min(TILE_M, N_NODES - row0);
    const int wr   = wid * 16;

    float accM[8][4], accS[8][4];
#pragma unroll
    for (int t = 0; t < 8; t++)
#pragma unroll
        for (int j = 0; j < 4; j++) { accM[t][j] = 0.f; accS[t][j] = 0.f; }

    for (int kc = 0; kc < 4; kc++) {
        {
            const float4* gf = (const float4*)(feat + (size_t)row0 * IN_F);
#pragma unroll
            for (int it = 0; it < 8; it++) {
                const int e  = tid + it * 256;
                const int r  = e >> 4;
                const int kg = e & 15;
                __nv_bfloat162 hp[2], lp[2];
                if (r < nrows) {
                    const float4 f = gf[r * 64 + kc * 16 + kg];
                    const __nv_bfloat16 h0 = __float2bfloat16(f.x);
                    const __nv_bfloat16 h1 = __float2bfloat16(f.y);
                    const __nv_bfloat16 h2 = __float2bfloat16(f.z);
                    const __nv_bfloat16 h3 = __float2bfloat16(f.w);
                    hp[0] = __nv_bfloat162(h0, h1); hp[1] = __nv_bfloat162(h2, h3);
                    lp[0] = __nv_bfloat162(__float2bfloat16(f.x - __bfloat162float(h0)),
                                           __float2bfloat16(f.y - __bfloat162float(h1)));
                    lp[1] = __nv_bfloat162(__float2bfloat16(f.z - __bfloat162float(h2)),
                                           __float2bfloat16(f.w - __bfloat162float(h3)));
                } else {
                    hp[0] = hp[1] = lp[0] = lp[1] = __nv_bfloat162(__nv_bfloat16(0.f), __nv_bfloat16(0.f));
                }
                *(uint2*)(Ah + r * APITCH + kg * 4) = *(uint2*)hp;
                *(uint2*)(Al + r * APITCH + kg * 4) = *(uint2*)lp;
            }
        }
#pragma unroll
        for (int it = 0; it < 16; it++) {
            const int e   = tid + it * 256;
            const int buf = e >> 10;
            const int r   = (e >> 4) & 63;
            const int kg  = e & 15;
            *(uint2*)(Bs + (buf * 64 + r) * APITCH + kg * 4) =
                *(const uint2*)(&g_wfrag[buf][r * IN_F + kc * 64 + kg * 4]);
        }
        __syncthreads();

#pragma unroll
        for (int ks = 0; ks < 4; ks++) {
            const int k0 = ks * 16 + tq * 2;
            uint32_t ah[4], al[4];
            const __nv_bfloat16* ar = Ah + (wr + gid) * APITCH;
            ah[0] = *(const uint32_t*)(ar + k0);
            ah[1] = *(const uint32_t*)(ar + 8 * APITCH + k0);
            ah[2] = *(const uint32_t*)(ar + k0 + 8);
            ah[3] = *(const uint32_t*)(ar + 8 * APITCH + k0 + 8);
            const __nv_bfloat16* arl = Al + (wr + gid) * APITCH;
            al[0] = *(const uint32_t*)(arl + k0);
            al[1] = *(const uint32_t*)(arl + 8 * APITCH + k0);
            al[2] = *(const uint32_t*)(arl + k0 + 8);
            al[3] = *(const uint32_t*)(arl + 8 * APITCH + k0 + 8);

#pragma unroll
            for (int nt = 0; nt < 8; nt++) {
                const int n = nt * 8 + gid;
                const __nv_bfloat16* b0p = Bs + n * APITCH;
                const __nv_bfloat16* b1p = Bs + (64 + n) * APITCH;
                const __nv_bfloat16* b2p = Bs + (128 + n) * APITCH;
                const __nv_bfloat16* b3p = Bs + (192 + n) * APITCH;
                const uint32_t mh0 = *(const uint32_t*)(b0p + k0);
                const uint32_t mh1 = *(const uint32_t*)(b0p + k0 + 8);
                const uint32_t ml0 = *(const uint32_t*)(b1p + k0);
                const uint32_t ml1 = *(const uint32_t*)(b1p + k0 + 8);
                const uint32_t sh0 = *(const uint32_t*)(b2p + k0);
                const uint32_t sh1 = *(const uint32_t*)(b2p + k0 + 8);
                const uint32_t sl0 = *(const uint32_t*)(b3p + k0);
                const uint32_t sl1 = *(const uint32_t*)(b3p + k0 + 8);
                mma16816(accM[nt], ah, mh0, mh1);
                mma16816(accM[nt], al, mh0, mh1);
                mma16816(accM[nt], ah, ml0, ml1);
                mma16816(accS[nt], ah, sh0, sh1);
                mma16816(accS[nt], al, sh0, sh1);
                mma16816(accS[nt], ah, sl0, sl1);
            }
        }
        __syncthreads();
    }

    // epilogue: lane-local activations -> interleaved g_msg[row][128]
#pragma unroll
    for (int t = 0; t < 8; t++) {
        const int n = t * 8 + tq * 2;
#pragma unroll
        for (int h = 0; h < 2; h++) {
            const int row = row0 + wr + gid + h * 8;
            if (row < N_NODES) {
                const float s0 = fmaxf(accS[t][2 * h + 0], 0.f);
                const float s1 = fmaxf(accS[t][2 * h + 1], 0.f);
                const float a0 = expf(-s0), a1 = expf(-s1);
                const float m0 = accM[t][2 * h + 0];
                const float m1 = accM[t][2 * h + 1];
                const float mi0 = (m0 > 0.f) ? m0 : (expf(m0) - 1.f);
                const float mi1 = (m1 > 0.f) ? m1 : (expf(m1) - 1.f);
                float* rowp = g_msg + (size_t)row * 128;
                *(float2*)(rowp + n)      = make_float2(mi0 * a0, mi1 * a1);
                *(float2*)(rowp + 64 + n) = make_float2(s0 * a0 * a0, s1 * a1 * a1);
            }
        }
    }
}

// =================== CSR gather: one contiguous 512B read per edge ==========
// Warp per dst node; lane c reads g_msg[src][c*4 .. c*4+3]:
//   lanes 0..15 cover miu (scale a1), lanes 16..31 cover sigma (scale a2).
__global__ __launch_bounds__(256) void gather_kernel(float* __restrict__ out)
{
    const int w = (blockIdx.x * 256 + threadIdx.x) >> 5;
    if (w >= N_NODES) return;
    const int lane = threadIdx.x & 31;
    const bool isMiu = lane < 16;

    const int beg = g_off[w];
    const int end = g_off[w + 1];

    float4 acc = make_float4(0.f, 0.f, 0.f, 0.f);
    for (int j = beg; j < end; j++) {
        const int4 ed = g_edges[j];                       // warp-broadcast
        const float sc = isMiu ? __int_as_float(ed.y) : __int_as_float(ed.z);
        const float4 v = ((const float4*)(g_msg + (size_t)ed.x * 128))[lane];
        acc.x = fmaf(v.x, sc, acc.x);
        acc.y = fmaf(v.y, sc, acc.y);
        acc.z = fmaf(v.z, sc, acc.z);
        acc.w = fmaf(v.w, sc, acc.w);
    }

    float* dstb = isMiu ? out + (size_t)w * OUT_F + lane * 4
                        : out + ((size_t)N_NODES + w) * OUT_F + (lane - 16) * 4;
    *(float4*)dstb = acc;
}

// =================== launch: fork/join overlap of CSR build vs GEMM =========
extern "C" void kernel_launch(void* const* d_in, const int* in_sizes, int n_in,
                              void* d_out, int out_size)
{
    const float* feat = (const float*)d_in[0];
    const void*  esrc = d_in[1];
    const void*  edst = d_in[2];
    const float* a1   = (const float*)d_in[3];
    const float* a2   = (const float*)d_in[4];
    const float* wm   = (const float*)d_in[5];
    const float* ws   = (const float*)d_in[6];
    float*       out  = (float*)d_out;
    const int E = in_sizes[3];

    static int inited = 0;
    static cudaStream_t s1;
    static cudaEvent_t eFork, eJoin;
    if (!inited) {
        cudaFuncSetAttribute(gemm_mma_kernel,
                             cudaFuncAttributeMaxDynamicSharedMemorySize, SM_BYTES);
        cudaStreamCreateWithFlags(&s1, cudaStreamNonBlocking);
        cudaEventCreateWithFlags(&eFork, cudaEventDisableTiming);
        cudaEventCreateWithFlags(&eJoin, cudaEventDisableTiming);
        inited = 1;
    }

    // fork: CSR-build chain on s1, GEMM chain on the capture stream
    cudaEventRecord(eFork, 0);
    cudaStreamWaitEvent(s1, eFork, 0);

    probe_kernel<<<1, 1, 0, s1>>>(esrc);
    zero_kernel<<<SCAN_B, 256, 0, s1>>>();
    hist_kernel<<<(E + 255) / 256, 256, 0, s1>>>(edst, E);
    scan1_kernel<<<SCAN_B, 256, 0, s1>>>();
    scan2_kernel<<<1, 256, 0, s1>>>();
    scan3_kernel<<<SCAN_B, 256, 0, s1>>>();
    fill_kernel<<<(E + 255) / 256, 256, 0, s1>>>(esrc, edst, a1, a2, E);
    cudaEventRecord(eJoin, s1);

    prep_w_kernel<<<128, 256>>>(wm, ws);
    gemm_mma_kernel<<<GEMM_BLOCKS, 256, SM_BYTES>>>(feat);

    // join: gather needs both CSR and messages
    cudaStreamWaitEvent(0, eJoin, 0);
    const long long threads = (long long)N_NODES * 32;
    gather_kernel<<<(int)((threads + 255) / 256), 256>>>(out);
}